// round 15
// baseline (speedup 1.0000x reference)
#include <cuda_runtime.h>
#include <cuda_fp16.h>
#include <math.h>
#include <stdint.h>

#define Bsz  128
#define HW   512
#define Pp   64
#define ND   4
#define HWHW 262144

// ---------------- scratch (static device globals) ---------------------------
__device__ float g_G  [2 * Bsz * ND * Pp * Pp];
__device__ float g_cs [2 * Bsz * ND * Pp];
__device__ float g_csp[2 * Bsz * 4 * 2 * 256];       // [z][b][mt][wm][256]
__device__ float2 g_statp[Bsz * 16];                 // per-chunk (sum, sumsq)
__device__ float g_meanv[Bsz];
__device__ float g_stdv [Bsz];
__device__ float g_xbd [ND * Bsz * 4096];            // per-depth normalized contribs

__device__ __half g_xf [33554432];   // fp16 x (row-major; also serves x^T GEMM)
__device__ __half g_w1f[262144];     // gemm1 weights, [n][k]
__device__ __half g_w2f[262144];     // gemm2 weights
// o-halves of the two GEMMs, [b][k=512][m=256], fp16
__device__ __half g_ojf[16777216];
__device__ __half g_oif[16777216];
// p weights, [d][k=512][n=64], fp16
__device__ __half g_pjf[131072];
__device__ __half g_pif[131072];

// ---------------- helpers (plain sm_103-legal PTX) ---------------------------
__device__ __forceinline__ uint32_t smem_u32(const void* p) {
    uint32_t a;
    asm("{ .reg .u64 t; cvta.to.shared.u64 t, %1; cvt.u32.u64 %0, t; }" : "=r"(a) : "l"(p));
    return a;
}
#define CP_ASYNC16(dst, src) \
    asm volatile("cp.async.cg.shared.global [%0], [%1], 16;" :: "r"(dst), "l"(src))
#define CP_COMMIT() asm volatile("cp.async.commit_group;" ::: "memory")
#define CP_WAIT(n)  asm volatile("cp.async.wait_group %0;" :: "n"(n) : "memory")

__device__ __forceinline__ void ldm_x4(uint32_t* r, uint32_t addr) {
    asm volatile("ldmatrix.sync.aligned.m8n8.x4.shared.b16 {%0,%1,%2,%3}, [%4];"
                 : "=r"(r[0]), "=r"(r[1]), "=r"(r[2]), "=r"(r[3]) : "r"(addr));
}
__device__ __forceinline__ void ldm_x4t(uint32_t* r, uint32_t addr) {
    asm volatile("ldmatrix.sync.aligned.m8n8.x4.trans.shared.b16 {%0,%1,%2,%3}, [%4];"
                 : "=r"(r[0]), "=r"(r[1]), "=r"(r[2]), "=r"(r[3]) : "r"(addr));
}
__device__ __forceinline__ void mma16816f(float* c, const uint32_t* a, const uint32_t* b) {
    asm volatile(
        "mma.sync.aligned.m16n8k16.row.col.f32.f16.f16.f32 "
        "{%0,%1,%2,%3}, {%4,%5,%6,%7}, {%8,%9}, {%0,%1,%2,%3};"
        : "+f"(c[0]), "+f"(c[1]), "+f"(c[2]), "+f"(c[3])
        : "r"(a[0]), "r"(a[1]), "r"(a[2]), "r"(a[3]), "r"(b[0]), "r"(b[1]));
}
#define SWZ(o) ((o) ^ (((o) >> 3) & 0x70))

// ---------------- prep: big-GEMM weights -> [n][k] fp16 ----------------------
__global__ void __launch_bounds__(256) convw_kernel(const float* __restrict__ o_xj,
                                                    const float* __restrict__ o_rel_xj,
                                                    const float* __restrict__ o_xi,
                                                    const float* __restrict__ o_rel_xi) {
    int n = blockIdx.x, side = blockIdx.y, t = threadIdx.x;
    const float* w = (side == 0) ? ((n < 256) ? o_xj : o_rel_xj)
                                 : ((n < 256) ? o_xi : o_rel_xi);
    int nn = n & 255, d = nn >> 6, c = nn & 63;
    __half* of = side ? g_w2f : g_w1f;
    #pragma unroll
    for (int i = 0; i < 2; i++) {
        int k = t + i * 256;
        of[n * HW + k] = __float2half_rn(w[d * (HW * Pp) + k * Pp + c]);
    }
}

// ---------------- prep: p weights -> fp16 ([d][k][n] layout) -----------------
__global__ void __launch_bounds__(256) convp_kernel(const float* __restrict__ p_xj,
                                                    const float* __restrict__ p_xi) {
    int i = blockIdx.x * 256 + threadIdx.x;     // 0..131071
    int side = blockIdx.y;
    const float* src = side ? p_xi : p_xj;
    __half* of = side ? g_pif : g_pjf;
    of[i] = __float2half_rn(src[i]);
}

// ---------------- prep: x -> fp16 (row-major only) + stat partials -----------
__global__ void __launch_bounds__(256) convx_kernel(const float* __restrict__ x) {
    __shared__ float rs[256], rq[256];
    int b = blockIdx.y, chunk = blockIdx.x;     // 16 chunks of 16384 floats
    int t = threadIdx.x;
    size_t base = (size_t)b * HWHW + (size_t)chunk * 16384;
    const float4* src = (const float4*)(x + base);
    __half2* dst = (__half2*)(g_xf + base);
    float ps = 0.f, pq = 0.f;
    #pragma unroll
    for (int i = 0; i < 16; i++) {
        int idx = t + i * 256;
        float4 v = src[idx];
        ps += v.x + v.y + v.z + v.w;
        pq += v.x * v.x + v.y * v.y + v.z * v.z + v.w * v.w;
        dst[idx * 2]     = __floats2half2_rn(v.x, v.y);
        dst[idx * 2 + 1] = __floats2half2_rn(v.z, v.w);
    }
    rs[t] = ps; rq[t] = pq;
    for (int off = 128; off > 0; off >>= 1) {
        __syncthreads();
        if (t < off) { rs[t] += rs[t + off]; rq[t] += rq[t + off]; }
    }
    if (t == 0) g_statp[b * 16 + chunk] = make_float2(rs[0], rq[0]);
}

// ---------------- mma.sync GEMM: X @ Wcat (single-pass fp16) -----------------
// CTA 128x256, warps 2(M)x4(N), warp tile 64x64, K chunks 64, 3-stage pipeline.
// nt=0 CTAs produce the o-half; nt=1 CTAs produce the rel colsums.
#define STG_BYTES 49152
#define NSTG 3
#define OFF_A 0
#define OFF_B 16384
#define GEMM_DYNSM (NSTG * STG_BYTES)

template<int Z>
__global__ void __launch_bounds__(256, 1) gemm_mma() {
    extern __shared__ __align__(16) unsigned char smp[];
    uint32_t sbase = smem_u32(smp);

    int t = threadIdx.x, lane = t & 31, w = t >> 5;
    int wm = w >> 2, wn = w & 3;
    int mt = blockIdx.x >> 1, nt = blockIdx.x & 1;
    int b = blockIdx.y;
    int m0 = mt * 128, n0 = nt * 256;

    const __half* xs = g_xf + (size_t)b * HWHW;
    const __half* ws = Z ? g_w2f : g_w1f;

    // ---- per-thread cp.async descriptors ----
    uint32_t aoff[4], adst[4], boff[8], bdst[8];
    const uint32_t astep = (Z == 0) ? 64u : 64u * HW;
    #pragma unroll
    for (int i = 0; i < 4; i++) {
        int u = t + i * 256;
        int row = u >> 3, seg = u & 7;
        if (Z == 0) {
            adst[i] = OFF_A + SWZ(row * 128 + seg * 16);
            aoff[i] = (uint32_t)((m0 + row) * HW + seg * 8);
        } else {
            int mh = u >> 9, k = (u >> 3) & 63;
            adst[i] = OFF_A + mh * 8192 + SWZ(k * 128 + seg * 16);
            aoff[i] = (uint32_t)(k * HW + m0 + mh * 64 + seg * 8);
        }
    }
    #pragma unroll
    for (int i = 0; i < 8; i++) {
        int u = t + i * 256;
        int row = u >> 3, seg = u & 7;
        bdst[i] = OFF_B + SWZ(row * 128 + seg * 16);
        boff[i] = (uint32_t)((n0 + row) * HW + seg * 8);
    }

    // ---- per-thread ldmatrix address components (hoisted swizzle) ----
    uint32_t aRow0 = 0, aColk[4], aRowT[4], aColTmi[4];
    if (Z == 0) {
        int a_row = (lane & 15), a_cb = (lane >> 4) * 16;
        aRow0 = OFF_A + (uint32_t)((wm * 64 + a_row) * 128);
        uint32_t m = (uint32_t)((a_row & 7) << 4);
        #pragma unroll
        for (int ks = 0; ks < 4; ks++) aColk[ks] = ((uint32_t)(ks * 32 + a_cb)) ^ m;
    } else {
        int a_rT = (lane & 7) + ((lane >> 4) & 1) * 8;
        int a_cT = ((lane >> 3) & 1) * 16;
        uint32_t m = (uint32_t)((a_rT & 7) << 4);
        #pragma unroll
        for (int ks = 0; ks < 4; ks++) aRowT[ks] = OFF_A + (uint32_t)((ks * 16 + a_rT) * 128);
        #pragma unroll
        for (int mi = 0; mi < 4; mi++) aColTmi[mi] = ((uint32_t)(mi * 32 + a_cT)) ^ m;
    }
    uint32_t bRow0, bColk[4];
    {
        int b_row = (lane & 7) + ((lane >> 4) & 1) * 8;
        int b_cb  = ((lane >> 3) & 1) * 16;
        uint32_t m = (uint32_t)((b_row & 7) << 4);
        bRow0 = OFF_B + (uint32_t)((wn * 64 + b_row) * 128);
        #pragma unroll
        for (int ks = 0; ks < 4; ks++) bColk[ks] = ((uint32_t)(ks * 32 + b_cb)) ^ m;
    }

    float acc[4][8][4];
    #pragma unroll
    for (int mi = 0; mi < 4; mi++)
        #pragma unroll
        for (int ni = 0; ni < 8; ni++)
            #pragma unroll
            for (int q = 0; q < 4; q++) acc[mi][ni][q] = 0.f;

    // prologue: issue chunks 0 and 1
    #pragma unroll
    for (int c = 0; c < 2; c++) {
        uint32_t tb = sbase + c * STG_BYTES;
        #pragma unroll
        for (int i = 0; i < 4; i++)
            CP_ASYNC16(tb + adst[i], xs + aoff[i] + c * astep);
        #pragma unroll
        for (int i = 0; i < 8; i++)
            CP_ASYNC16(tb + bdst[i], ws + boff[i] + c * 64u);
        CP_COMMIT();
    }

    #pragma unroll 1
    for (int kt = 0; kt < 8; kt++) {
        if (kt < 7) { CP_WAIT(1); } else { CP_WAIT(0); }
        __syncthreads();

        if (kt + 2 < 8) {
            uint32_t tb = sbase + ((kt + 2) % NSTG) * STG_BYTES;
            uint32_t c = (uint32_t)(kt + 2);
            #pragma unroll
            for (int i = 0; i < 4; i++)
                CP_ASYNC16(tb + adst[i], xs + aoff[i] + c * astep);
            #pragma unroll
            for (int i = 0; i < 8; i++)
                CP_ASYNC16(tb + bdst[i], ws + boff[i] + c * 64u);
            CP_COMMIT();
        }

        uint32_t tb = sbase + (kt % NSTG) * STG_BYTES;
        #pragma unroll
        for (int ks = 0; ks < 4; ks++) {
            uint32_t ah[4][4], bh[8][2];
            if (Z == 0) {
                uint32_t base = tb + aRow0 + aColk[ks];
                #pragma unroll
                for (int mi = 0; mi < 4; mi++)
                    ldm_x4(ah[mi], base + mi * 2048);
            } else {
                uint32_t base = tb + wm * 8192 + aRowT[ks];
                #pragma unroll
                for (int mi = 0; mi < 4; mi++)
                    ldm_x4t(ah[mi], base + aColTmi[mi]);
            }
            {
                uint32_t base = tb + bRow0 + bColk[ks];
                #pragma unroll
                for (int np = 0; np < 4; np++) {
                    uint32_t rh[4];
                    ldm_x4(rh, base + np * 2048);
                    bh[np * 2][0] = rh[0]; bh[np * 2][1] = rh[1];
                    bh[np * 2 + 1][0] = rh[2]; bh[np * 2 + 1][1] = rh[3];
                }
            }
            #pragma unroll
            for (int mi = 0; mi < 4; mi++)
                #pragma unroll
                for (int ni = 0; ni < 8; ni++)
                    mma16816f(acc[mi][ni], ah[mi], bh[ni]);
        }
    }
    __syncthreads();

    int gq = lane >> 2, tig = lane & 3;
    if (nt == 0) {
        // o-half: fp16, layout [b][k=row][m=col(0..255)]
        __half* of = Z ? g_oif : g_ojf;
        size_t bb = (size_t)b * (512 * 256);
        #pragma unroll
        for (int mi = 0; mi < 4; mi++) {
            int row0 = m0 + wm * 64 + mi * 16 + gq;
            #pragma unroll
            for (int ni = 0; ni < 8; ni++) {
                int col = wn * 64 + ni * 8 + tig * 2;
                *(__half2*)&of[bb + (size_t)row0 * 256 + col] =
                    __floats2half2_rn(acc[mi][ni][0], acc[mi][ni][1]);
                *(__half2*)&of[bb + (size_t)(row0 + 8) * 256 + col] =
                    __floats2half2_rn(acc[mi][ni][2], acc[mi][ni][3]);
            }
        }
    } else {
        // rel-half: exp colsum partials, layout [z][b][mt][wm][256]
        size_t p = (((size_t)(Z * Bsz + b) * 4 + mt) * 2 + wm) * 256;
        #pragma unroll
        for (int ni = 0; ni < 8; ni++) {
            float s0 = 0.f, s1 = 0.f;
            #pragma unroll
            for (int mi = 0; mi < 4; mi++) {
                s0 += expf(acc[mi][ni][0]) + expf(acc[mi][ni][2]);
                s1 += expf(acc[mi][ni][1]) + expf(acc[mi][ni][3]);
            }
            #pragma unroll
            for (int o = 4; o < 32; o <<= 1) {
                s0 += __shfl_xor_sync(0xFFFFFFFFu, s0, o);
                s1 += __shfl_xor_sync(0xFFFFFFFFu, s1, o);
            }
            if (gq == 0) {
                int cl = wn * 64 + ni * 8 + tig * 2;
                g_csp[p + cl]     = s0;
                g_csp[p + cl + 1] = s1;
            }
        }
    }
}

// ---------------- fold colsum partials (+ per-batch stats in block 0) --------
__global__ void __launch_bounds__(256) csred_kernel() {
    int i = blockIdx.x * 256 + threadIdx.x;     // 0..65535
    int side = i >> 15;
    int r = i & 32767;
    int b = r >> 8;
    int cl = r & 255;
    int d = cl >> 6, c = cl & 63;
    size_t base = ((size_t)(side * Bsz + b) * 8) * 256;
    float s = 0.f;
    #pragma unroll
    for (int mtw = 0; mtw < 8; mtw++) s += g_csp[base + (size_t)mtw * 256 + cl];
    g_cs[((side * Bsz + b) * ND + d) * 64 + c] = s;

    if (blockIdx.x == 0 && threadIdx.x < 128) {
        int bb = threadIdx.x;
        float ps = 0.f, pq = 0.f;
        #pragma unroll
        for (int ch = 0; ch < 16; ch++) {
            float2 p = g_statp[bb * 16 + ch];
            ps += p.x; pq += p.y;
        }
        float n = (float)HWHW;
        float mean = ps / n;
        float var  = (pq - ps * ps / n) / (n - 1.f);
        g_meanv[bb] = mean * 64.f;
        g_stdv[bb]  = sqrtf(var) * 64.f;
    }
}

// ---------------- stage-2 via mma: G = A_o^T @ p_x  (64x64, K=512) -----------
#define S2_STG 16384
#define S2_A 0
#define S2_W 8192
#define S2_DYNSM (2 * S2_STG)

__global__ void __launch_bounds__(128) stage2_mma() {
    extern __shared__ __align__(16) unsigned char smp2[];
    uint32_t sbase = smem_u32(smp2);

    int t = threadIdx.x, lane = t & 31, wn = t >> 5;   // 4 warps, each 16 N-cols
    int d = blockIdx.x, side = blockIdx.y, b = blockIdx.z;

    const __half* A = (side ? g_oif : g_ojf) + (size_t)b * (512 * 256) + d * 64;
    const __half* W = (side ? g_pif : g_pjf) + (size_t)d * (512 * 64);

    int a_r = (lane & 7) + ((lane >> 4) & 1) * 8;   // k within 16
    int a_c = ((lane >> 3) & 1) * 16;               // m byte within 32
    int w_r = (lane & 7) + ((lane >> 3) & 1) * 8;   // k within 16
    int w_c = ((lane >> 4) & 1) * 16;               // n byte within 32

    float acc[4][2][4];
    #pragma unroll
    for (int mi = 0; mi < 4; mi++)
        #pragma unroll
        for (int ni = 0; ni < 2; ni++)
            #pragma unroll
            for (int q = 0; q < 4; q++) acc[mi][ni][q] = 0.f;

    {
        uint32_t tb = sbase;
        #pragma unroll
        for (int i = 0; i < 4; i++) {
            int u = t + i * 128;
            int row = u >> 3, seg = u & 7;
            uint32_t so = SWZ(row * 128 + seg * 16);
            CP_ASYNC16(tb + S2_A + so, A + (size_t)row * 256 + seg * 8);
            CP_ASYNC16(tb + S2_W + so, W + (size_t)row * 64 + seg * 8);
        }
        CP_COMMIT();
    }

    #pragma unroll 1
    for (int kt = 0; kt < 8; kt++) {
        if (kt + 1 < 8) {
            uint32_t tb = sbase + ((kt + 1) & 1) * S2_STG;
            int k0 = (kt + 1) * 64;
            #pragma unroll
            for (int i = 0; i < 4; i++) {
                int u = t + i * 128;
                int row = u >> 3, seg = u & 7;
                uint32_t so = SWZ(row * 128 + seg * 16);
                CP_ASYNC16(tb + S2_A + so, A + (size_t)(k0 + row) * 256 + seg * 8);
                CP_ASYNC16(tb + S2_W + so, W + (size_t)(k0 + row) * 64 + seg * 8);
            }
            CP_COMMIT();
            CP_WAIT(1);
        } else {
            CP_WAIT(0);
        }
        __syncthreads();

        uint32_t tb = sbase + (kt & 1) * S2_STG;
        #pragma unroll
        for (int ks = 0; ks < 4; ks++) {
            uint32_t ah[4][4], wh[2][2];
            #pragma unroll
            for (int mi = 0; mi < 4; mi++) {
                uint32_t off = SWZ((uint32_t)((ks * 16 + a_r) * 128 + mi * 32 + a_c));
                ldm_x4t(ah[mi], tb + S2_A + off);
            }
            {
                uint32_t off = SWZ((uint32_t)((ks * 16 + w_r) * 128 + wn * 32 + w_c));
                uint32_t rh[4];
                ldm_x4t(rh, tb + S2_W + off);
                wh[0][0] = rh[0]; wh[0][1] = rh[1]; wh[1][0] = rh[2]; wh[1][1] = rh[3];
            }
            #pragma unroll
            for (int mi = 0; mi < 4; mi++)
                #pragma unroll
                for (int ni = 0; ni < 2; ni++)
                    mma16816f(acc[mi][ni], ah[mi], wh[ni]);
        }
        __syncthreads();
    }

    float* g = g_G + (size_t)((side * Bsz + b) * ND + d) * 4096;
    int gq = lane >> 2, tig = lane & 3;
    #pragma unroll
    for (int mi = 0; mi < 4; mi++) {
        int m = mi * 16 + gq;
        #pragma unroll
        for (int ni = 0; ni < 2; ni++) {
            int n = wn * 16 + ni * 8 + tig * 2;
            *(float2*)&g[m * 64 + n]       = make_float2(acc[mi][ni][0], acc[mi][ni][1]);
            *(float2*)&g[(m + 8) * 64 + n] = make_float2(acc[mi][ni][2], acc[mi][ni][3]);
        }
    }
}

// ---------------- final: one CTA per (d, b) ----------------------------------
#define FINAL_SMEM_FLOATS (4096 + 4160 + 4096 + 256 + 256 + 64 + 64 + 64 + 64 + 16)

__global__ void __launch_bounds__(256) final_depth(const float* __restrict__ p_rel_xj,
                                                   const float* __restrict__ p_rel_xi) {
    extern __shared__ float sm[];
    float* sGj  = sm;
    float* sGi  = sGj + 4096;   // 64x65 padded
    float* sWR  = sGi + 4160;
    float* red  = sWR + 4096;
    float* red2 = red + 256;
    float* sfj  = red2 + 256;
    float* sfi  = sfj + 64;
    float* sCS  = sfi + 64;
    float* sOCS = sCS + 64;
    float* sTOT = sOCS + 64;    // [0]=p total, [1]=o total

    int d = blockIdx.x, b = blockIdx.y, t = threadIdx.x;
    float xmean = g_meanv[b], xstd = g_stdv[b];

    int prw = (t >> 4) * 4, qcw = (t & 15) * 4;
    int col = t & 63, grp = t >> 6;

    #pragma unroll
    for (int i = 0; i < 16; i++) {
        int id = t + i * 256;
        int p = id >> 6, q = id & 63;
        sGj[p * 64 + q] = g_G[(size_t)((0 * Bsz + b) * ND + d) * 4096 + id];
        sGi[p * 65 + q] = g_G[(size_t)((1 * Bsz + b) * ND + d) * 4096 + id];
    }
    __syncthreads();

    for (int side = 0; side < 2; side++) {
        const float* prel = (side == 0 ? p_rel_xj : p_rel_xi) + d * 4096;
        #pragma unroll
        for (int i = 0; i < 16; i++) sWR[t + i * 256] = prel[t + i * 256];
        if (t < 64) sOCS[t] = g_cs[((side * Bsz + b) * ND + d) * 64 + t];
        __syncthreads();

        const float* G = side ? sGi : sGj;
        int gs = side ? 65 : 64;
        float acc[4][4];
        #pragma unroll
        for (int i = 0; i < 4; i++)
            #pragma unroll
            for (int j = 0; j < 4; j++) acc[i][j] = 0.f;
        #pragma unroll 8
        for (int kk = 0; kk < 64; kk++) {
            float a0 = G[(prw + 0) * gs + kk];
            float a1 = G[(prw + 1) * gs + kk];
            float a2 = G[(prw + 2) * gs + kk];
            float a3 = G[(prw + 3) * gs + kk];
            float4 w4 = *(const float4*)&sWR[kk * 64 + qcw];
            acc[0][0] = fmaf(a0, w4.x, acc[0][0]); acc[0][1] = fmaf(a0, w4.y, acc[0][1]);
            acc[0][2] = fmaf(a0, w4.z, acc[0][2]); acc[0][3] = fmaf(a0, w4.w, acc[0][3]);
            acc[1][0] = fmaf(a1, w4.x, acc[1][0]); acc[1][1] = fmaf(a1, w4.y, acc[1][1]);
            acc[1][2] = fmaf(a1, w4.z, acc[1][2]); acc[1][3] = fmaf(a1, w4.w, acc[1][3]);
            acc[2][0] = fmaf(a2, w4.x, acc[2][0]); acc[2][1] = fmaf(a2, w4.y, acc[2][1]);
            acc[2][2] = fmaf(a2, w4.z, acc[2][2]); acc[2][3] = fmaf(a2, w4.w, acc[2][3]);
            acc[3][0] = fmaf(a3, w4.x, acc[3][0]); acc[3][1] = fmaf(a3, w4.y, acc[3][1]);
            acc[3][2] = fmaf(a3, w4.z, acc[3][2]); acc[3][3] = fmaf(a3, w4.w, acc[3][3]);
        }
        __syncthreads();
        #pragma unroll
        for (int i = 0; i < 4; i++)
            #pragma unroll
            for (int j = 0; j < 4; j++)
                sWR[(prw + i) * 64 + qcw + j] = expf(acc[i][j]);
        __syncthreads();

        float s = 0.f;
        #pragma unroll
        for (int r = 0; r < 16; r++) s += sWR[(grp * 16 + r) * 64 + col];
        red[t] = s; __syncthreads();
        if (t < 64) sCS[t] = red[t] + red[t + 64] + red[t + 128] + red[t + 192];
        __syncthreads();
        if (t == 0) {
            float tp = 0.f, to = 0.f;
            for (int i = 0; i < 64; i++) { tp += sCS[i]; to += sOCS[i]; }
            sTOT[0] = tp; sTOT[1] = to;
        }
        __syncthreads();
        if (t < 64) {
            float f = sqrtf((sOCS[t] * sTOT[0]) / (sTOT[1] * sCS[t]));
            (side ? sfi : sfj)[t] = f;
        }
        __syncthreads();
    }

    float xb[16]; float s = 0.f, ss = 0.f;
    #pragma unroll
    for (int i = 0; i < 16; i++) {
        int id = t + i * 256;
        int p = id >> 6, q = id & 63;
        float v = sGj[p * 64 + q] * sfj[p] + sGi[q * 65 + p] * sfi[q];
        xb[i] = v; s += v; ss += v * v;
    }
    red[t] = s; red2[t] = ss; __syncthreads();
    for (int off = 128; off > 0; off >>= 1) {
        if (t < off) { red[t] += red[t + off]; red2[t] += red2[t + off]; }
        __syncthreads();
    }
    float n = 4096.f;
    float mean = red[0] / n;
    float var  = (red2[0] - red[0] * red[0] / n) / (n - 1.f);
    float istd = 1.f / (sqrtf(var) + 1e-5f);
    float* ob = g_xbd + (size_t)(d * Bsz + b) * 4096;
    #pragma unroll
    for (int i = 0; i < 16; i++)
        ob[t + i * 256] = (xb[i] - mean) * istd * xstd + xmean;
}

// ---------------- accumulate per-depth contributions (fixed d order) ---------
__global__ void __launch_bounds__(256) accum_kernel(float* __restrict__ out) {
    int i = blockIdx.x * 256 + threadIdx.x;      // 0 .. Bsz*4096-1
    int b = i >> 12, idx = i & 4095;
    float s = 0.f;
    #pragma unroll
    for (int d = 0; d < ND; d++)
        s += g_xbd[(size_t)(d * Bsz + b) * 4096 + idx];
    out[i] = s;
}

// ---------------- launcher ---------------------------------------------------
extern "C" void kernel_launch(void* const* d_in, const int* in_sizes, int n_in,
                              void* d_out, int out_size) {
    const float* x        = (const float*)d_in[0];
    const float* o_xj     = (const float*)d_in[1];
    const float* o_xi     = (const float*)d_in[2];
    const float* p_xj     = (const float*)d_in[3];
    const float* p_xi     = (const float*)d_in[4];
    const float* o_rel_xj = (const float*)d_in[5];
    const float* o_rel_xi = (const float*)d_in[6];
    const float* p_rel_xj = (const float*)d_in[7];
    const float* p_rel_xi = (const float*)d_in[8];
    float* out = (float*)d_out;

    cudaFuncSetAttribute(final_depth, cudaFuncAttributeMaxDynamicSharedMemorySize,
                         FINAL_SMEM_FLOATS * sizeof(float));
    cudaFuncSetAttribute(gemm_mma<0>, cudaFuncAttributeMaxDynamicSharedMemorySize,
                         GEMM_DYNSM);
    cudaFuncSetAttribute(gemm_mma<1>, cudaFuncAttributeMaxDynamicSharedMemorySize,
                         GEMM_DYNSM);
    cudaFuncSetAttribute(stage2_mma, cudaFuncAttributeMaxDynamicSharedMemorySize,
                         S2_DYNSM);

    // gemm_mma<0> is launch #4 so ncu (-s 5 -c 1) profiles it
    convw_kernel<<<dim3(512, 2), 256>>>(o_xj, o_rel_xj, o_xi, o_rel_xi);
    convp_kernel<<<dim3(512, 2), 256>>>(p_xj, p_xi);
    convx_kernel<<<dim3(16, Bsz), 256>>>(x);
    gemm_mma<0><<<dim3(8, Bsz), 256, GEMM_DYNSM>>>();
    gemm_mma<1><<<dim3(8, Bsz), 256, GEMM_DYNSM>>>();
    csred_kernel<<<256, 256>>>();
    stage2_mma<<<dim3(ND, 2, Bsz), 128, S2_DYNSM>>>();
    final_depth<<<dim3(ND, Bsz), 256, FINAL_SMEM_FLOATS * sizeof(float)>>>(p_rel_xj, p_rel_xi);
    accum_kernel<<<Bsz * 4096 / 256, 256>>>(out);
}

// round 16
// speedup vs baseline: 1.0938x; 1.0938x over previous
#include <cuda_runtime.h>
#include <cuda_fp16.h>
#include <math.h>
#include <stdint.h>

#define Bsz  128
#define HW   512
#define Pp   64
#define ND   4
#define HWHW 262144

// ---------------- scratch (static device globals) ---------------------------
__device__ float g_G  [2 * Bsz * ND * Pp * Pp];
__device__ float g_cs [2 * Bsz * ND * Pp];
__device__ float g_csp[2 * Bsz * 2 * 4 * 2 * 128];   // [z][b][nt2][mt][wm][128]
__device__ float2 g_statp[Bsz * 16];                 // per-chunk (sum, sumsq)
__device__ float g_meanv[Bsz];
__device__ float g_stdv [Bsz];
__device__ float g_xbd [ND * Bsz * 4096];            // per-depth normalized contribs

__device__ __half g_xf [33554432];   // fp16 x (row-major; also serves x^T GEMM)
__device__ __half g_w1f[262144];     // gemm1 weights, [n][k]
__device__ __half g_w2f[262144];     // gemm2 weights
// o-halves of the two GEMMs, [b][k=512][m=256], fp16
__device__ __half g_ojf[16777216];
__device__ __half g_oif[16777216];
// p weights, [d][k=512][n=64], fp16
__device__ __half g_pjf[131072];
__device__ __half g_pif[131072];

// ---------------- helpers (plain sm_103-legal PTX) ---------------------------
__device__ __forceinline__ uint32_t smem_u32(const void* p) {
    uint32_t a;
    asm("{ .reg .u64 t; cvta.to.shared.u64 t, %1; cvt.u32.u64 %0, t; }" : "=r"(a) : "l"(p));
    return a;
}
#define CP_ASYNC16(dst, src) \
    asm volatile("cp.async.cg.shared.global [%0], [%1], 16;" :: "r"(dst), "l"(src))
#define CP_COMMIT() asm volatile("cp.async.commit_group;" ::: "memory")
#define CP_WAIT(n)  asm volatile("cp.async.wait_group %0;" :: "n"(n) : "memory")

__device__ __forceinline__ void ldm_x4(uint32_t* r, uint32_t addr) {
    asm volatile("ldmatrix.sync.aligned.m8n8.x4.shared.b16 {%0,%1,%2,%3}, [%4];"
                 : "=r"(r[0]), "=r"(r[1]), "=r"(r[2]), "=r"(r[3]) : "r"(addr));
}
__device__ __forceinline__ void ldm_x4t(uint32_t* r, uint32_t addr) {
    asm volatile("ldmatrix.sync.aligned.m8n8.x4.trans.shared.b16 {%0,%1,%2,%3}, [%4];"
                 : "=r"(r[0]), "=r"(r[1]), "=r"(r[2]), "=r"(r[3]) : "r"(addr));
}
__device__ __forceinline__ void mma16816f(float* c, const uint32_t* a, const uint32_t* b) {
    asm volatile(
        "mma.sync.aligned.m16n8k16.row.col.f32.f16.f16.f32 "
        "{%0,%1,%2,%3}, {%4,%5,%6,%7}, {%8,%9}, {%0,%1,%2,%3};"
        : "+f"(c[0]), "+f"(c[1]), "+f"(c[2]), "+f"(c[3])
        : "r"(a[0]), "r"(a[1]), "r"(a[2]), "r"(a[3]), "r"(b[0]), "r"(b[1]));
}
#define SWZ(o) ((o) ^ (((o) >> 3) & 0x70))

// ---------------- prep: big-GEMM weights -> [n][k] fp16 ----------------------
__global__ void __launch_bounds__(256) convw_kernel(const float* __restrict__ o_xj,
                                                    const float* __restrict__ o_rel_xj,
                                                    const float* __restrict__ o_xi,
                                                    const float* __restrict__ o_rel_xi) {
    int n = blockIdx.x, side = blockIdx.y, t = threadIdx.x;
    const float* w = (side == 0) ? ((n < 256) ? o_xj : o_rel_xj)
                                 : ((n < 256) ? o_xi : o_rel_xi);
    int nn = n & 255, d = nn >> 6, c = nn & 63;
    __half* of = side ? g_w2f : g_w1f;
    #pragma unroll
    for (int i = 0; i < 2; i++) {
        int k = t + i * 256;
        of[n * HW + k] = __float2half_rn(w[d * (HW * Pp) + k * Pp + c]);
    }
}

// ---------------- prep: p weights -> fp16 ([d][k][n] layout) -----------------
__global__ void __launch_bounds__(256) convp_kernel(const float* __restrict__ p_xj,
                                                    const float* __restrict__ p_xi) {
    int i = blockIdx.x * 256 + threadIdx.x;     // 0..131071
    int side = blockIdx.y;
    const float* src = side ? p_xi : p_xj;
    __half* of = side ? g_pif : g_pjf;
    of[i] = __float2half_rn(src[i]);
}

// ---------------- prep: x -> fp16 (row-major only) + stat partials -----------
__global__ void __launch_bounds__(256) convx_kernel(const float* __restrict__ x) {
    __shared__ float rs[256], rq[256];
    int b = blockIdx.y, chunk = blockIdx.x;     // 16 chunks of 16384 floats
    int t = threadIdx.x;
    size_t base = (size_t)b * HWHW + (size_t)chunk * 16384;
    const float4* src = (const float4*)(x + base);
    __half2* dst = (__half2*)(g_xf + base);
    float ps = 0.f, pq = 0.f;
    #pragma unroll
    for (int i = 0; i < 16; i++) {
        int idx = t + i * 256;
        float4 v = src[idx];
        ps += v.x + v.y + v.z + v.w;
        pq += v.x * v.x + v.y * v.y + v.z * v.z + v.w * v.w;
        dst[idx * 2]     = __floats2half2_rn(v.x, v.y);
        dst[idx * 2 + 1] = __floats2half2_rn(v.z, v.w);
    }
    rs[t] = ps; rq[t] = pq;
    for (int off = 128; off > 0; off >>= 1) {
        __syncthreads();
        if (t < off) { rs[t] += rs[t + off]; rq[t] += rq[t + off]; }
    }
    if (t == 0) g_statp[b * 16 + chunk] = make_float2(rs[0], rq[0]);
}

// ---------------- mma.sync GEMM: X @ Wcat (single-pass fp16) -----------------
// CTA 128x128, 128 threads = 4 warps (2M x 2N), warp tile 64x64.
// K chunks 64, 3-stage pipeline, single barrier per chunk, 2 CTAs/SM.
#define STG_BYTES 32768
#define NSTG 3
#define OFF_A 0
#define OFF_B 16384
#define GEMM_DYNSM (NSTG * STG_BYTES)

template<int Z>
__global__ void __launch_bounds__(128, 2) gemm_mma() {
    extern __shared__ __align__(16) unsigned char smp[];
    uint32_t sbase = smem_u32(smp);

    int t = threadIdx.x, lane = t & 31, w = t >> 5;
    int wm = w >> 1, wn = w & 1;
    int mt = blockIdx.x >> 2, nt = blockIdx.x & 3;
    int b = blockIdx.y;
    int m0 = mt * 128, n0 = nt * 128;

    const __half* xs = g_xf + (size_t)b * HWHW;
    const __half* ws = Z ? g_w2f : g_w1f;

    // ---- per-thread cp.async descriptors (8 A-units + 8 B-units) ----
    uint32_t aoff[8], adst[8], boff[8], bdst[8];
    const uint32_t astep = (Z == 0) ? 64u : 64u * HW;
    #pragma unroll
    for (int i = 0; i < 8; i++) {
        int u = t + i * 128;
        int row = u >> 3, seg = u & 7;
        if (Z == 0) {
            adst[i] = OFF_A + SWZ(row * 128 + seg * 16);
            aoff[i] = (uint32_t)((m0 + row) * HW + seg * 8);
        } else {
            int mh = u >> 9, k = (u >> 3) & 63;
            adst[i] = OFF_A + mh * 8192 + SWZ(k * 128 + seg * 16);
            aoff[i] = (uint32_t)(k * HW + m0 + mh * 64 + seg * 8);
        }
        bdst[i] = OFF_B + SWZ(row * 128 + seg * 16);
        boff[i] = (uint32_t)((n0 + row) * HW + seg * 8);
    }

    // ---- per-thread ldmatrix address components (hoisted swizzle) ----
    uint32_t aRow0 = 0, aColk[4], aRowT[4], aColTmi[4];
    if (Z == 0) {
        int a_row = (lane & 15), a_cb = (lane >> 4) * 16;
        aRow0 = OFF_A + (uint32_t)((wm * 64 + a_row) * 128);
        uint32_t m = (uint32_t)((a_row & 7) << 4);
        #pragma unroll
        for (int ks = 0; ks < 4; ks++) aColk[ks] = ((uint32_t)(ks * 32 + a_cb)) ^ m;
    } else {
        int a_rT = (lane & 7) + ((lane >> 4) & 1) * 8;
        int a_cT = ((lane >> 3) & 1) * 16;
        uint32_t m = (uint32_t)((a_rT & 7) << 4);
        #pragma unroll
        for (int ks = 0; ks < 4; ks++) aRowT[ks] = OFF_A + (uint32_t)((ks * 16 + a_rT) * 128);
        #pragma unroll
        for (int mi = 0; mi < 4; mi++) aColTmi[mi] = ((uint32_t)(mi * 32 + a_cT)) ^ m;
    }
    uint32_t bRow0, bColk[4];
    {
        int b_row = (lane & 7) + ((lane >> 4) & 1) * 8;
        int b_cb  = ((lane >> 3) & 1) * 16;
        uint32_t m = (uint32_t)((b_row & 7) << 4);
        bRow0 = OFF_B + (uint32_t)((wn * 64 + b_row) * 128);
        #pragma unroll
        for (int ks = 0; ks < 4; ks++) bColk[ks] = ((uint32_t)(ks * 32 + b_cb)) ^ m;
    }

    float acc[4][8][4];
    #pragma unroll
    for (int mi = 0; mi < 4; mi++)
        #pragma unroll
        for (int ni = 0; ni < 8; ni++)
            #pragma unroll
            for (int q = 0; q < 4; q++) acc[mi][ni][q] = 0.f;

    // prologue: issue chunks 0 and 1
    #pragma unroll
    for (int c = 0; c < 2; c++) {
        uint32_t tb = sbase + c * STG_BYTES;
        #pragma unroll
        for (int i = 0; i < 8; i++) {
            CP_ASYNC16(tb + adst[i], xs + aoff[i] + c * astep);
            CP_ASYNC16(tb + bdst[i], ws + boff[i] + c * 64u);
        }
        CP_COMMIT();
    }

    #pragma unroll 1
    for (int kt = 0; kt < 8; kt++) {
        if (kt < 7) { CP_WAIT(1); } else { CP_WAIT(0); }
        __syncthreads();

        if (kt + 2 < 8) {
            uint32_t tb = sbase + ((kt + 2) % NSTG) * STG_BYTES;
            uint32_t c = (uint32_t)(kt + 2);
            #pragma unroll
            for (int i = 0; i < 8; i++) {
                CP_ASYNC16(tb + adst[i], xs + aoff[i] + c * astep);
                CP_ASYNC16(tb + bdst[i], ws + boff[i] + c * 64u);
            }
            CP_COMMIT();
        }

        uint32_t tb = sbase + (kt % NSTG) * STG_BYTES;
        #pragma unroll
        for (int ks = 0; ks < 4; ks++) {
            uint32_t ah[4][4], bh[8][2];
            if (Z == 0) {
                uint32_t base = tb + aRow0 + aColk[ks];
                #pragma unroll
                for (int mi = 0; mi < 4; mi++)
                    ldm_x4(ah[mi], base + mi * 2048);
            } else {
                uint32_t base = tb + wm * 8192 + aRowT[ks];
                #pragma unroll
                for (int mi = 0; mi < 4; mi++)
                    ldm_x4t(ah[mi], base + aColTmi[mi]);
            }
            {
                uint32_t base = tb + bRow0 + bColk[ks];
                #pragma unroll
                for (int np = 0; np < 4; np++) {
                    uint32_t rh[4];
                    ldm_x4(rh, base + np * 2048);
                    bh[np * 2][0] = rh[0]; bh[np * 2][1] = rh[1];
                    bh[np * 2 + 1][0] = rh[2]; bh[np * 2 + 1][1] = rh[3];
                }
            }
            #pragma unroll
            for (int mi = 0; mi < 4; mi++)
                #pragma unroll
                for (int ni = 0; ni < 8; ni++)
                    mma16816f(acc[mi][ni], ah[mi], bh[ni]);
        }
    }
    __syncthreads();

    int gq = lane >> 2, tig = lane & 3;
    if (nt < 2) {
        // o-half: fp16, layout [b][k=row][m=col(0..255)]
        __half* of = Z ? g_oif : g_ojf;
        size_t bb = (size_t)b * (512 * 256);
        #pragma unroll
        for (int mi = 0; mi < 4; mi++) {
            int row0 = m0 + wm * 64 + mi * 16 + gq;
            #pragma unroll
            for (int ni = 0; ni < 8; ni++) {
                int col = nt * 128 + wn * 64 + ni * 8 + tig * 2;
                *(__half2*)&of[bb + (size_t)row0 * 256 + col] =
                    __floats2half2_rn(acc[mi][ni][0], acc[mi][ni][1]);
                *(__half2*)&of[bb + (size_t)(row0 + 8) * 256 + col] =
                    __floats2half2_rn(acc[mi][ni][2], acc[mi][ni][3]);
            }
        }
    } else {
        // rel-half: exp colsum partials, layout [z][b][nt2][mt][wm][128]
        size_t p = ((((size_t)(Z * Bsz + b) * 2 + (nt - 2)) * 4 + mt) * 2 + wm) * 128;
        #pragma unroll
        for (int ni = 0; ni < 8; ni++) {
            float s0 = 0.f, s1 = 0.f;
            #pragma unroll
            for (int mi = 0; mi < 4; mi++) {
                s0 += expf(acc[mi][ni][0]) + expf(acc[mi][ni][2]);
                s1 += expf(acc[mi][ni][1]) + expf(acc[mi][ni][3]);
            }
            #pragma unroll
            for (int o = 4; o < 32; o <<= 1) {
                s0 += __shfl_xor_sync(0xFFFFFFFFu, s0, o);
                s1 += __shfl_xor_sync(0xFFFFFFFFu, s1, o);
            }
            if (gq == 0) {
                int cl = wn * 64 + ni * 8 + tig * 2;
                g_csp[p + cl]     = s0;
                g_csp[p + cl + 1] = s1;
            }
        }
    }
}

// ---------------- fold colsum partials (+ per-batch stats in block 0) --------
__global__ void __launch_bounds__(256) csred_kernel() {
    int i = blockIdx.x * 256 + threadIdx.x;     // 0..65535
    int side = i >> 15;
    int r = i & 32767;
    int b = r >> 8;
    int dc = r & 255;
    int d = dc >> 6, c = dc & 63;
    int nt2 = d >> 1;
    int cl = (d & 1) * 64 + c;
    size_t base = (((size_t)(side * Bsz + b) * 2 + nt2) * 4) * 2 * 128;
    float s = 0.f;
    #pragma unroll
    for (int mtw = 0; mtw < 8; mtw++) s += g_csp[base + (size_t)mtw * 128 + cl];
    g_cs[((side * Bsz + b) * ND + d) * 64 + c] = s;

    if (blockIdx.x == 0 && threadIdx.x < 128) {
        int bb = threadIdx.x;
        float ps = 0.f, pq = 0.f;
        #pragma unroll
        for (int ch = 0; ch < 16; ch++) {
            float2 p = g_statp[bb * 16 + ch];
            ps += p.x; pq += p.y;
        }
        float n = (float)HWHW;
        float mean = ps / n;
        float var  = (pq - ps * ps / n) / (n - 1.f);
        g_meanv[bb] = mean * 64.f;
        g_stdv[bb]  = sqrtf(var) * 64.f;
    }
}

// ---------------- stage-2 via mma: G = A_o^T @ p_x  (64x64, K=512) -----------
#define S2_STG 16384
#define S2_A 0
#define S2_W 8192
#define S2_DYNSM (2 * S2_STG)

__global__ void __launch_bounds__(128) stage2_mma() {
    extern __shared__ __align__(16) unsigned char smp2[];
    uint32_t sbase = smem_u32(smp2);

    int t = threadIdx.x, lane = t & 31, wn = t >> 5;   // 4 warps, each 16 N-cols
    int d = blockIdx.x, side = blockIdx.y, b = blockIdx.z;

    const __half* A = (side ? g_oif : g_ojf) + (size_t)b * (512 * 256) + d * 64;
    const __half* W = (side ? g_pif : g_pjf) + (size_t)d * (512 * 64);

    int a_r = (lane & 7) + ((lane >> 4) & 1) * 8;   // k within 16
    int a_c = ((lane >> 3) & 1) * 16;               // m byte within 32
    int w_r = (lane & 7) + ((lane >> 3) & 1) * 8;   // k within 16
    int w_c = ((lane >> 4) & 1) * 16;               // n byte within 32

    float acc[4][2][4];
    #pragma unroll
    for (int mi = 0; mi < 4; mi++)
        #pragma unroll
        for (int ni = 0; ni < 2; ni++)
            #pragma unroll
            for (int q = 0; q < 4; q++) acc[mi][ni][q] = 0.f;

    {
        uint32_t tb = sbase;
        #pragma unroll
        for (int i = 0; i < 4; i++) {
            int u = t + i * 128;
            int row = u >> 3, seg = u & 7;
            uint32_t so = SWZ(row * 128 + seg * 16);
            CP_ASYNC16(tb + S2_A + so, A + (size_t)row * 256 + seg * 8);
            CP_ASYNC16(tb + S2_W + so, W + (size_t)row * 64 + seg * 8);
        }
        CP_COMMIT();
    }

    #pragma unroll 1
    for (int kt = 0; kt < 8; kt++) {
        if (kt + 1 < 8) {
            uint32_t tb = sbase + ((kt + 1) & 1) * S2_STG;
            int k0 = (kt + 1) * 64;
            #pragma unroll
            for (int i = 0; i < 4; i++) {
                int u = t + i * 128;
                int row = u >> 3, seg = u & 7;
                uint32_t so = SWZ(row * 128 + seg * 16);
                CP_ASYNC16(tb + S2_A + so, A + (size_t)(k0 + row) * 256 + seg * 8);
                CP_ASYNC16(tb + S2_W + so, W + (size_t)(k0 + row) * 64 + seg * 8);
            }
            CP_COMMIT();
            CP_WAIT(1);
        } else {
            CP_WAIT(0);
        }
        __syncthreads();

        uint32_t tb = sbase + (kt & 1) * S2_STG;
        #pragma unroll
        for (int ks = 0; ks < 4; ks++) {
            uint32_t ah[4][4], wh[2][2];
            #pragma unroll
            for (int mi = 0; mi < 4; mi++) {
                uint32_t off = SWZ((uint32_t)((ks * 16 + a_r) * 128 + mi * 32 + a_c));
                ldm_x4t(ah[mi], tb + S2_A + off);
            }
            {
                uint32_t off = SWZ((uint32_t)((ks * 16 + w_r) * 128 + wn * 32 + w_c));
                uint32_t rh[4];
                ldm_x4t(rh, tb + S2_W + off);
                wh[0][0] = rh[0]; wh[0][1] = rh[1]; wh[1][0] = rh[2]; wh[1][1] = rh[3];
            }
            #pragma unroll
            for (int mi = 0; mi < 4; mi++)
                #pragma unroll
                for (int ni = 0; ni < 2; ni++)
                    mma16816f(acc[mi][ni], ah[mi], wh[ni]);
        }
        __syncthreads();
    }

    float* g = g_G + (size_t)((side * Bsz + b) * ND + d) * 4096;
    int gq = lane >> 2, tig = lane & 3;
    #pragma unroll
    for (int mi = 0; mi < 4; mi++) {
        int m = mi * 16 + gq;
        #pragma unroll
        for (int ni = 0; ni < 2; ni++) {
            int n = wn * 16 + ni * 8 + tig * 2;
            *(float2*)&g[m * 64 + n]       = make_float2(acc[mi][ni][0], acc[mi][ni][1]);
            *(float2*)&g[(m + 8) * 64 + n] = make_float2(acc[mi][ni][2], acc[mi][ni][3]);
        }
    }
}

// ---------------- final: one CTA per (d, b) ----------------------------------
#define FINAL_SMEM_FLOATS (4096 + 4160 + 4096 + 256 + 256 + 64 + 64 + 64 + 64 + 16)

__global__ void __launch_bounds__(256) final_depth(const float* __restrict__ p_rel_xj,
                                                   const float* __restrict__ p_rel_xi) {
    extern __shared__ float sm[];
    float* sGj  = sm;
    float* sGi  = sGj + 4096;   // 64x65 padded
    float* sWR  = sGi + 4160;
    float* red  = sWR + 4096;
    float* red2 = red + 256;
    float* sfj  = red2 + 256;
    float* sfi  = sfj + 64;
    float* sCS  = sfi + 64;
    float* sOCS = sCS + 64;
    float* sTOT = sOCS + 64;    // [0]=p total, [1]=o total

    int d = blockIdx.x, b = blockIdx.y, t = threadIdx.x;
    float xmean = g_meanv[b], xstd = g_stdv[b];

    int prw = (t >> 4) * 4, qcw = (t & 15) * 4;
    int col = t & 63, grp = t >> 6;

    #pragma unroll
    for (int i = 0; i < 16; i++) {
        int id = t + i * 256;
        int p = id >> 6, q = id & 63;
        sGj[p * 64 + q] = g_G[(size_t)((0 * Bsz + b) * ND + d) * 4096 + id];
        sGi[p * 65 + q] = g_G[(size_t)((1 * Bsz + b) * ND + d) * 4096 + id];
    }
    __syncthreads();

    for (int side = 0; side < 2; side++) {
        const float* prel = (side == 0 ? p_rel_xj : p_rel_xi) + d * 4096;
        #pragma unroll
        for (int i = 0; i < 16; i++) sWR[t + i * 256] = prel[t + i * 256];
        if (t < 64) sOCS[t] = g_cs[((side * Bsz + b) * ND + d) * 64 + t];
        __syncthreads();

        const float* G = side ? sGi : sGj;
        int gs = side ? 65 : 64;
        float acc[4][4];
        #pragma unroll
        for (int i = 0; i < 4; i++)
            #pragma unroll
            for (int j = 0; j < 4; j++) acc[i][j] = 0.f;
        #pragma unroll 8
        for (int kk = 0; kk < 64; kk++) {
            float a0 = G[(prw + 0) * gs + kk];
            float a1 = G[(prw + 1) * gs + kk];
            float a2 = G[(prw + 2) * gs + kk];
            float a3 = G[(prw + 3) * gs + kk];
            float4 w4 = *(const float4*)&sWR[kk * 64 + qcw];
            acc[0][0] = fmaf(a0, w4.x, acc[0][0]); acc[0][1] = fmaf(a0, w4.y, acc[0][1]);
            acc[0][2] = fmaf(a0, w4.z, acc[0][2]); acc[0][3] = fmaf(a0, w4.w, acc[0][3]);
            acc[1][0] = fmaf(a1, w4.x, acc[1][0]); acc[1][1] = fmaf(a1, w4.y, acc[1][1]);
            acc[1][2] = fmaf(a1, w4.z, acc[1][2]); acc[1][3] = fmaf(a1, w4.w, acc[1][3]);
            acc[2][0] = fmaf(a2, w4.x, acc[2][0]); acc[2][1] = fmaf(a2, w4.y, acc[2][1]);
            acc[2][2] = fmaf(a2, w4.z, acc[2][2]); acc[2][3] = fmaf(a2, w4.w, acc[2][3]);
            acc[3][0] = fmaf(a3, w4.x, acc[3][0]); acc[3][1] = fmaf(a3, w4.y, acc[3][1]);
            acc[3][2] = fmaf(a3, w4.z, acc[3][2]); acc[3][3] = fmaf(a3, w4.w, acc[3][3]);
        }
        __syncthreads();
        #pragma unroll
        for (int i = 0; i < 4; i++)
            #pragma unroll
            for (int j = 0; j < 4; j++)
                sWR[(prw + i) * 64 + qcw + j] = expf(acc[i][j]);
        __syncthreads();

        float s = 0.f;
        #pragma unroll
        for (int r = 0; r < 16; r++) s += sWR[(grp * 16 + r) * 64 + col];
        red[t] = s; __syncthreads();
        if (t < 64) sCS[t] = red[t] + red[t + 64] + red[t + 128] + red[t + 192];
        __syncthreads();
        if (t == 0) {
            float tp = 0.f, to = 0.f;
            for (int i = 0; i < 64; i++) { tp += sCS[i]; to += sOCS[i]; }
            sTOT[0] = tp; sTOT[1] = to;
        }
        __syncthreads();
        if (t < 64) {
            float f = sqrtf((sOCS[t] * sTOT[0]) / (sTOT[1] * sCS[t]));
            (side ? sfi : sfj)[t] = f;
        }
        __syncthreads();
    }

    float xb[16]; float s = 0.f, ss = 0.f;
    #pragma unroll
    for (int i = 0; i < 16; i++) {
        int id = t + i * 256;
        int p = id >> 6, q = id & 63;
        float v = sGj[p * 64 + q] * sfj[p] + sGi[q * 65 + p] * sfi[q];
        xb[i] = v; s += v; ss += v * v;
    }
    red[t] = s; red2[t] = ss; __syncthreads();
    for (int off = 128; off > 0; off >>= 1) {
        if (t < off) { red[t] += red[t + off]; red2[t] += red2[t + off]; }
        __syncthreads();
    }
    float n = 4096.f;
    float mean = red[0] / n;
    float var  = (red2[0] - red[0] * red[0] / n) / (n - 1.f);
    float istd = 1.f / (sqrtf(var) + 1e-5f);
    float* ob = g_xbd + (size_t)(d * Bsz + b) * 4096;
    #pragma unroll
    for (int i = 0; i < 16; i++)
        ob[t + i * 256] = (xb[i] - mean) * istd * xstd + xmean;
}

// ---------------- accumulate per-depth contributions (fixed d order) ---------
__global__ void __launch_bounds__(256) accum_kernel(float* __restrict__ out) {
    int i = blockIdx.x * 256 + threadIdx.x;      // 0 .. Bsz*4096-1
    int b = i >> 12, idx = i & 4095;
    float s = 0.f;
    #pragma unroll
    for (int d = 0; d < ND; d++)
        s += g_xbd[(size_t)(d * Bsz + b) * 4096 + idx];
    out[i] = s;
}

// ---------------- launcher ---------------------------------------------------
extern "C" void kernel_launch(void* const* d_in, const int* in_sizes, int n_in,
                              void* d_out, int out_size) {
    const float* x        = (const float*)d_in[0];
    const float* o_xj     = (const float*)d_in[1];
    const float* o_xi     = (const float*)d_in[2];
    const float* p_xj     = (const float*)d_in[3];
    const float* p_xi     = (const float*)d_in[4];
    const float* o_rel_xj = (const float*)d_in[5];
    const float* o_rel_xi = (const float*)d_in[6];
    const float* p_rel_xj = (const float*)d_in[7];
    const float* p_rel_xi = (const float*)d_in[8];
    float* out = (float*)d_out;

    cudaFuncSetAttribute(final_depth, cudaFuncAttributeMaxDynamicSharedMemorySize,
                         FINAL_SMEM_FLOATS * sizeof(float));
    cudaFuncSetAttribute(gemm_mma<0>, cudaFuncAttributeMaxDynamicSharedMemorySize,
                         GEMM_DYNSM);
    cudaFuncSetAttribute(gemm_mma<1>, cudaFuncAttributeMaxDynamicSharedMemorySize,
                         GEMM_DYNSM);
    cudaFuncSetAttribute(stage2_mma, cudaFuncAttributeMaxDynamicSharedMemorySize,
                         S2_DYNSM);

    // gemm_mma<0> is launch #4 so ncu (-s 5 -c 1) profiles it
    convw_kernel<<<dim3(512, 2), 256>>>(o_xj, o_rel_xj, o_xi, o_rel_xi);
    convp_kernel<<<dim3(512, 2), 256>>>(p_xj, p_xi);
    convx_kernel<<<dim3(16, Bsz), 256>>>(x);
    gemm_mma<0><<<dim3(16, Bsz), 128, GEMM_DYNSM>>>();
    gemm_mma<1><<<dim3(16, Bsz), 128, GEMM_DYNSM>>>();
    csred_kernel<<<256, 256>>>();
    stage2_mma<<<dim3(ND, 2, Bsz), 128, S2_DYNSM>>>();
    final_depth<<<dim3(ND, Bsz), 256, FINAL_SMEM_FLOATS * sizeof(float)>>>(p_rel_xj, p_rel_xi);
    accum_kernel<<<Bsz * 4096 / 256, 256>>>(out);
}

// round 17
// speedup vs baseline: 1.1074x; 1.0125x over previous
#include <cuda_runtime.h>
#include <cuda_fp16.h>
#include <math.h>
#include <stdint.h>

#define Bsz  128
#define HW   512
#define Pp   64
#define ND   4
#define HWHW 262144

// ---------------- scratch (static device globals) ---------------------------
__device__ float g_G  [2 * Bsz * ND * Pp * Pp];
__device__ float g_cs [2 * Bsz * ND * Pp];
__device__ float g_csp[2 * Bsz * 2 * 4 * 2 * 128];   // [z][b][nt2][mt][wm][128]
__device__ float2 g_statp[Bsz * 16];                 // per-chunk (sum, sumsq)
__device__ float g_meanv[Bsz];
__device__ float g_stdv [Bsz];
__device__ float g_xbd [ND * Bsz * 4096];            // per-depth normalized contribs

__device__ __half g_xf [33554432];   // fp16 x (row-major; also serves x^T GEMM)
__device__ __half g_w1f[262144];     // gemm1 weights, [n][k]
__device__ __half g_w2f[262144];     // gemm2 weights
// o-halves of the two GEMMs, [b][k=512][m=256], fp16
__device__ __half g_ojf[16777216];
__device__ __half g_oif[16777216];
// p weights, [d][k=512][n=64], fp16
__device__ __half g_pjf[131072];
__device__ __half g_pif[131072];

// ---------------- helpers (plain sm_103-legal PTX) ---------------------------
__device__ __forceinline__ uint32_t smem_u32(const void* p) {
    uint32_t a;
    asm("{ .reg .u64 t; cvta.to.shared.u64 t, %1; cvt.u32.u64 %0, t; }" : "=r"(a) : "l"(p));
    return a;
}
#define CP_ASYNC16(dst, src) \
    asm volatile("cp.async.cg.shared.global [%0], [%1], 16;" :: "r"(dst), "l"(src))
#define CP_COMMIT() asm volatile("cp.async.commit_group;" ::: "memory")
#define CP_WAIT(n)  asm volatile("cp.async.wait_group %0;" :: "n"(n) : "memory")

__device__ __forceinline__ void ldm_x4(uint32_t* r, uint32_t addr) {
    asm volatile("ldmatrix.sync.aligned.m8n8.x4.shared.b16 {%0,%1,%2,%3}, [%4];"
                 : "=r"(r[0]), "=r"(r[1]), "=r"(r[2]), "=r"(r[3]) : "r"(addr));
}
__device__ __forceinline__ void ldm_x4t(uint32_t* r, uint32_t addr) {
    asm volatile("ldmatrix.sync.aligned.m8n8.x4.trans.shared.b16 {%0,%1,%2,%3}, [%4];"
                 : "=r"(r[0]), "=r"(r[1]), "=r"(r[2]), "=r"(r[3]) : "r"(addr));
}
__device__ __forceinline__ void mma16816f(float* c, const uint32_t* a, const uint32_t* b) {
    asm volatile(
        "mma.sync.aligned.m16n8k16.row.col.f32.f16.f16.f32 "
        "{%0,%1,%2,%3}, {%4,%5,%6,%7}, {%8,%9}, {%0,%1,%2,%3};"
        : "+f"(c[0]), "+f"(c[1]), "+f"(c[2]), "+f"(c[3])
        : "r"(a[0]), "r"(a[1]), "r"(a[2]), "r"(a[3]), "r"(b[0]), "r"(b[1]));
}
#define SWZ(o) ((o) ^ (((o) >> 3) & 0x70))

// ---------------- prep: big-GEMM weights -> [n][k] fp16 ----------------------
__global__ void __launch_bounds__(256) convw_kernel(const float* __restrict__ o_xj,
                                                    const float* __restrict__ o_rel_xj,
                                                    const float* __restrict__ o_xi,
                                                    const float* __restrict__ o_rel_xi) {
    int n = blockIdx.x, side = blockIdx.y, t = threadIdx.x;
    const float* w = (side == 0) ? ((n < 256) ? o_xj : o_rel_xj)
                                 : ((n < 256) ? o_xi : o_rel_xi);
    int nn = n & 255, d = nn >> 6, c = nn & 63;
    __half* of = side ? g_w2f : g_w1f;
    #pragma unroll
    for (int i = 0; i < 2; i++) {
        int k = t + i * 256;
        of[n * HW + k] = __float2half_rn(w[d * (HW * Pp) + k * Pp + c]);
    }
}

// ---------------- prep: p weights -> fp16 ([d][k][n] layout) -----------------
__global__ void __launch_bounds__(256) convp_kernel(const float* __restrict__ p_xj,
                                                    const float* __restrict__ p_xi) {
    int i = blockIdx.x * 256 + threadIdx.x;     // 0..131071
    int side = blockIdx.y;
    const float* src = side ? p_xi : p_xj;
    __half* of = side ? g_pif : g_pjf;
    of[i] = __float2half_rn(src[i]);
}

// ---------------- prep: x -> fp16 (row-major only) + stat partials -----------
__global__ void __launch_bounds__(256) convx_kernel(const float* __restrict__ x) {
    __shared__ float rs[256], rq[256];
    int b = blockIdx.y, chunk = blockIdx.x;     // 16 chunks of 16384 floats
    int t = threadIdx.x;
    size_t base = (size_t)b * HWHW + (size_t)chunk * 16384;
    const float4* src = (const float4*)(x + base);
    __half2* dst = (__half2*)(g_xf + base);
    float ps = 0.f, pq = 0.f;
    #pragma unroll
    for (int i = 0; i < 16; i++) {
        int idx = t + i * 256;
        float4 v = src[idx];
        ps += v.x + v.y + v.z + v.w;
        pq += v.x * v.x + v.y * v.y + v.z * v.z + v.w * v.w;
        dst[idx * 2]     = __floats2half2_rn(v.x, v.y);
        dst[idx * 2 + 1] = __floats2half2_rn(v.z, v.w);
    }
    rs[t] = ps; rq[t] = pq;
    for (int off = 128; off > 0; off >>= 1) {
        __syncthreads();
        if (t < off) { rs[t] += rs[t + off]; rq[t] += rq[t + off]; }
    }
    if (t == 0) g_statp[b * 16 + chunk] = make_float2(rs[0], rq[0]);
}

// ---------------- mma.sync GEMM: X @ Wcat (single-pass fp16) -----------------
// CTA 128x128, 128 threads = 4 warps (2M x 2N), warp tile 64x64.
// K chunks 64, 3-stage pipeline, single barrier per chunk, 2 CTAs/SM.
// cp.async descriptors reduced to 4 base regs + constant strides.
#define STG_BYTES 32768
#define NSTG 3
#define OFF_A 0
#define OFF_B 16384
#define GEMM_DYNSM (NSTG * STG_BYTES)

template<int Z>
__global__ void __launch_bounds__(128, 2) gemm_mma() {
    extern __shared__ __align__(16) unsigned char smp[];
    uint32_t sbase = smem_u32(smp);

    int t = threadIdx.x, lane = t & 31, w = t >> 5;
    int wm = w >> 1, wn = w & 1;
    int mt = blockIdx.x >> 2, nt = blockIdx.x & 3;
    int b = blockIdx.y;
    int m0 = mt * 128, n0 = nt * 128;

    const __half* xs = g_xf + (size_t)b * HWHW;
    const __half* ws = Z ? g_w2f : g_w1f;

    // ---- compact cp.async descriptors: 4 bases, constant strides ----
    // i-th unit (i=0..7): adst = adst0 + i*2048, bdst = bdst0 + i*2048
    //   Z=0: aoff = aoff0 + i*16*HW
    //   Z=1: aoff = aoff0 + (i&3)*16*HW + (i>>2)*64
    //   boff = boff0 + i*16*HW
    uint32_t adst0, aoff0, bdst0, boff0;
    {
        int row = t >> 3, seg = t & 7;
        if (Z == 0) {
            adst0 = OFF_A + SWZ(row * 128 + seg * 16);
            aoff0 = (uint32_t)((m0 + row) * HW + seg * 8);
        } else {
            adst0 = OFF_A + SWZ(row * 128 + seg * 16);
            aoff0 = (uint32_t)(row * HW + m0 + seg * 8);
        }
        bdst0 = OFF_B + SWZ(row * 128 + seg * 16);
        boff0 = (uint32_t)((n0 + row) * HW + seg * 8);
    }
    const uint32_t astep = (Z == 0) ? 64u : 64u * HW;

    // ---- per-thread ldmatrix address components (hoisted swizzle) ----
    uint32_t aRow0 = 0, aColk[4], aRowT[4], aColTmi[4];
    if (Z == 0) {
        int a_row = (lane & 15), a_cb = (lane >> 4) * 16;
        aRow0 = OFF_A + (uint32_t)((wm * 64 + a_row) * 128);
        uint32_t m = (uint32_t)((a_row & 7) << 4);
        #pragma unroll
        for (int ks = 0; ks < 4; ks++) aColk[ks] = ((uint32_t)(ks * 32 + a_cb)) ^ m;
    } else {
        int a_rT = (lane & 7) + ((lane >> 4) & 1) * 8;
        int a_cT = ((lane >> 3) & 1) * 16;
        uint32_t m = (uint32_t)((a_rT & 7) << 4);
        #pragma unroll
        for (int ks = 0; ks < 4; ks++) aRowT[ks] = OFF_A + (uint32_t)((ks * 16 + a_rT) * 128);
        #pragma unroll
        for (int mi = 0; mi < 4; mi++) aColTmi[mi] = ((uint32_t)(mi * 32 + a_cT)) ^ m;
    }
    uint32_t bRow0, bColk[4];
    {
        int b_row = (lane & 7) + ((lane >> 4) & 1) * 8;
        int b_cb  = ((lane >> 3) & 1) * 16;
        uint32_t m = (uint32_t)((b_row & 7) << 4);
        bRow0 = OFF_B + (uint32_t)((wn * 64 + b_row) * 128);
        #pragma unroll
        for (int ks = 0; ks < 4; ks++) bColk[ks] = ((uint32_t)(ks * 32 + b_cb)) ^ m;
    }

    float acc[4][8][4];
    #pragma unroll
    for (int mi = 0; mi < 4; mi++)
        #pragma unroll
        for (int ni = 0; ni < 8; ni++)
            #pragma unroll
            for (int q = 0; q < 4; q++) acc[mi][ni][q] = 0.f;

    // prologue: issue chunks 0 and 1
    #pragma unroll
    for (int c = 0; c < 2; c++) {
        uint32_t tb = sbase + c * STG_BYTES;
        #pragma unroll
        for (int i = 0; i < 8; i++) {
            uint32_t ao = (Z == 0) ? aoff0 + (uint32_t)i * 16u * HW
                                   : aoff0 + (uint32_t)(i & 3) * 16u * HW + (uint32_t)(i >> 2) * 64u;
            CP_ASYNC16(tb + adst0 + i * 2048, xs + ao + c * astep);
            CP_ASYNC16(tb + bdst0 + i * 2048, ws + boff0 + (uint32_t)i * 16u * HW + c * 64u);
        }
        CP_COMMIT();
    }

    #pragma unroll 1
    for (int kt = 0; kt < 8; kt++) {
        if (kt < 7) { CP_WAIT(1); } else { CP_WAIT(0); }
        __syncthreads();

        if (kt + 2 < 8) {
            uint32_t tb = sbase + ((kt + 2) % NSTG) * STG_BYTES;
            uint32_t c = (uint32_t)(kt + 2);
            #pragma unroll
            for (int i = 0; i < 8; i++) {
                uint32_t ao = (Z == 0) ? aoff0 + (uint32_t)i * 16u * HW
                                       : aoff0 + (uint32_t)(i & 3) * 16u * HW + (uint32_t)(i >> 2) * 64u;
                CP_ASYNC16(tb + adst0 + i * 2048, xs + ao + c * astep);
                CP_ASYNC16(tb + bdst0 + i * 2048, ws + boff0 + (uint32_t)i * 16u * HW + c * 64u);
            }
            CP_COMMIT();
        }

        uint32_t tb = sbase + (kt % NSTG) * STG_BYTES;
        #pragma unroll
        for (int ks = 0; ks < 4; ks++) {
            uint32_t ah[4][4], bh[8][2];
            if (Z == 0) {
                uint32_t base = tb + aRow0 + aColk[ks];
                #pragma unroll
                for (int mi = 0; mi < 4; mi++)
                    ldm_x4(ah[mi], base + mi * 2048);
            } else {
                uint32_t base = tb + wm * 8192 + aRowT[ks];
                #pragma unroll
                for (int mi = 0; mi < 4; mi++)
                    ldm_x4t(ah[mi], base + aColTmi[mi]);
            }
            {
                uint32_t base = tb + bRow0 + bColk[ks];
                #pragma unroll
                for (int np = 0; np < 4; np++) {
                    uint32_t rh[4];
                    ldm_x4(rh, base + np * 2048);
                    bh[np * 2][0] = rh[0]; bh[np * 2][1] = rh[1];
                    bh[np * 2 + 1][0] = rh[2]; bh[np * 2 + 1][1] = rh[3];
                }
            }
            #pragma unroll
            for (int mi = 0; mi < 4; mi++)
                #pragma unroll
                for (int ni = 0; ni < 8; ni++)
                    mma16816f(acc[mi][ni], ah[mi], bh[ni]);
        }
    }
    __syncthreads();

    int gq = lane >> 2, tig = lane & 3;
    if (nt < 2) {
        // o-half: fp16, layout [b][k=row][m=col(0..255)]
        __half* of = Z ? g_oif : g_ojf;
        size_t bb = (size_t)b * (512 * 256);
        #pragma unroll
        for (int mi = 0; mi < 4; mi++) {
            int row0 = m0 + wm * 64 + mi * 16 + gq;
            #pragma unroll
            for (int ni = 0; ni < 8; ni++) {
                int col = nt * 128 + wn * 64 + ni * 8 + tig * 2;
                *(__half2*)&of[bb + (size_t)row0 * 256 + col] =
                    __floats2half2_rn(acc[mi][ni][0], acc[mi][ni][1]);
                *(__half2*)&of[bb + (size_t)(row0 + 8) * 256 + col] =
                    __floats2half2_rn(acc[mi][ni][2], acc[mi][ni][3]);
            }
        }
    } else {
        // rel-half: exp colsum partials, layout [z][b][nt2][mt][wm][128]
        size_t p = ((((size_t)(Z * Bsz + b) * 2 + (nt - 2)) * 4 + mt) * 2 + wm) * 128;
        #pragma unroll
        for (int ni = 0; ni < 8; ni++) {
            float s0 = 0.f, s1 = 0.f;
            #pragma unroll
            for (int mi = 0; mi < 4; mi++) {
                s0 += expf(acc[mi][ni][0]) + expf(acc[mi][ni][2]);
                s1 += expf(acc[mi][ni][1]) + expf(acc[mi][ni][3]);
            }
            #pragma unroll
            for (int o = 4; o < 32; o <<= 1) {
                s0 += __shfl_xor_sync(0xFFFFFFFFu, s0, o);
                s1 += __shfl_xor_sync(0xFFFFFFFFu, s1, o);
            }
            if (gq == 0) {
                int cl = wn * 64 + ni * 8 + tig * 2;
                g_csp[p + cl]     = s0;
                g_csp[p + cl + 1] = s1;
            }
        }
    }
}

// ---------------- fold colsum partials (+ per-batch stats in block 0) --------
__global__ void __launch_bounds__(256) csred_kernel() {
    int i = blockIdx.x * 256 + threadIdx.x;     // 0..65535
    int side = i >> 15;
    int r = i & 32767;
    int b = r >> 8;
    int dc = r & 255;
    int d = dc >> 6, c = dc & 63;
    int nt2 = d >> 1;
    int cl = (d & 1) * 64 + c;
    size_t base = (((size_t)(side * Bsz + b) * 2 + nt2) * 4) * 2 * 128;
    float s = 0.f;
    #pragma unroll
    for (int mtw = 0; mtw < 8; mtw++) s += g_csp[base + (size_t)mtw * 128 + cl];
    g_cs[((side * Bsz + b) * ND + d) * 64 + c] = s;

    if (blockIdx.x == 0 && threadIdx.x < 128) {
        int bb = threadIdx.x;
        float ps = 0.f, pq = 0.f;
        #pragma unroll
        for (int ch = 0; ch < 16; ch++) {
            float2 p = g_statp[bb * 16 + ch];
            ps += p.x; pq += p.y;
        }
        float n = (float)HWHW;
        float mean = ps / n;
        float var  = (pq - ps * ps / n) / (n - 1.f);
        g_meanv[bb] = mean * 64.f;
        g_stdv[bb]  = sqrtf(var) * 64.f;
    }
}

// ---------------- stage-2 via mma: G = A_o^T @ p_x  (64x64, K=512) -----------
#define S2_STG 16384
#define S2_A 0
#define S2_W 8192
#define S2_DYNSM (2 * S2_STG)

__global__ void __launch_bounds__(128) stage2_mma() {
    extern __shared__ __align__(16) unsigned char smp2[];
    uint32_t sbase = smem_u32(smp2);

    int t = threadIdx.x, lane = t & 31, wn = t >> 5;   // 4 warps, each 16 N-cols
    int d = blockIdx.x, side = blockIdx.y, b = blockIdx.z;

    const __half* A = (side ? g_oif : g_ojf) + (size_t)b * (512 * 256) + d * 64;
    const __half* W = (side ? g_pif : g_pjf) + (size_t)d * (512 * 64);

    int a_r = (lane & 7) + ((lane >> 4) & 1) * 8;   // k within 16
    int a_c = ((lane >> 3) & 1) * 16;               // m byte within 32
    int w_r = (lane & 7) + ((lane >> 3) & 1) * 8;   // k within 16
    int w_c = ((lane >> 4) & 1) * 16;               // n byte within 32

    float acc[4][2][4];
    #pragma unroll
    for (int mi = 0; mi < 4; mi++)
        #pragma unroll
        for (int ni = 0; ni < 2; ni++)
            #pragma unroll
            for (int q = 0; q < 4; q++) acc[mi][ni][q] = 0.f;

    {
        uint32_t tb = sbase;
        #pragma unroll
        for (int i = 0; i < 4; i++) {
            int u = t + i * 128;
            int row = u >> 3, seg = u & 7;
            uint32_t so = SWZ(row * 128 + seg * 16);
            CP_ASYNC16(tb + S2_A + so, A + (size_t)row * 256 + seg * 8);
            CP_ASYNC16(tb + S2_W + so, W + (size_t)row * 64 + seg * 8);
        }
        CP_COMMIT();
    }

    #pragma unroll 1
    for (int kt = 0; kt < 8; kt++) {
        if (kt + 1 < 8) {
            uint32_t tb = sbase + ((kt + 1) & 1) * S2_STG;
            int k0 = (kt + 1) * 64;
            #pragma unroll
            for (int i = 0; i < 4; i++) {
                int u = t + i * 128;
                int row = u >> 3, seg = u & 7;
                uint32_t so = SWZ(row * 128 + seg * 16);
                CP_ASYNC16(tb + S2_A + so, A + (size_t)(k0 + row) * 256 + seg * 8);
                CP_ASYNC16(tb + S2_W + so, W + (size_t)(k0 + row) * 64 + seg * 8);
            }
            CP_COMMIT();
            CP_WAIT(1);
        } else {
            CP_WAIT(0);
        }
        __syncthreads();

        uint32_t tb = sbase + (kt & 1) * S2_STG;
        #pragma unroll
        for (int ks = 0; ks < 4; ks++) {
            uint32_t ah[4][4], wh[2][2];
            #pragma unroll
            for (int mi = 0; mi < 4; mi++) {
                uint32_t off = SWZ((uint32_t)((ks * 16 + a_r) * 128 + mi * 32 + a_c));
                ldm_x4t(ah[mi], tb + S2_A + off);
            }
            {
                uint32_t off = SWZ((uint32_t)((ks * 16 + w_r) * 128 + wn * 32 + w_c));
                uint32_t rh[4];
                ldm_x4t(rh, tb + S2_W + off);
                wh[0][0] = rh[0]; wh[0][1] = rh[1]; wh[1][0] = rh[2]; wh[1][1] = rh[3];
            }
            #pragma unroll
            for (int mi = 0; mi < 4; mi++)
                #pragma unroll
                for (int ni = 0; ni < 2; ni++)
                    mma16816f(acc[mi][ni], ah[mi], wh[ni]);
        }
        __syncthreads();
    }

    float* g = g_G + (size_t)((side * Bsz + b) * ND + d) * 4096;
    int gq = lane >> 2, tig = lane & 3;
    #pragma unroll
    for (int mi = 0; mi < 4; mi++) {
        int m = mi * 16 + gq;
        #pragma unroll
        for (int ni = 0; ni < 2; ni++) {
            int n = wn * 16 + ni * 8 + tig * 2;
            *(float2*)&g[m * 64 + n]       = make_float2(acc[mi][ni][0], acc[mi][ni][1]);
            *(float2*)&g[(m + 8) * 64 + n] = make_float2(acc[mi][ni][2], acc[mi][ni][3]);
        }
    }
}

// ---------------- final: one CTA per (d, b) ----------------------------------
#define FINAL_SMEM_FLOATS (4096 + 4160 + 4096 + 256 + 256 + 64 + 64 + 64 + 64 + 16)

__global__ void __launch_bounds__(256) final_depth(const float* __restrict__ p_rel_xj,
                                                   const float* __restrict__ p_rel_xi) {
    extern __shared__ float sm[];
    float* sGj  = sm;
    float* sGi  = sGj + 4096;   // 64x65 padded
    float* sWR  = sGi + 4160;
    float* red  = sWR + 4096;
    float* red2 = red + 256;
    float* sfj  = red2 + 256;
    float* sfi  = sfj + 64;
    float* sCS  = sfi + 64;
    float* sOCS = sCS + 64;
    float* sTOT = sOCS + 64;    // [0]=p total, [1]=o total

    int d = blockIdx.x, b = blockIdx.y, t = threadIdx.x;
    float xmean = g_meanv[b], xstd = g_stdv[b];

    int prw = (t >> 4) * 4, qcw = (t & 15) * 4;
    int col = t & 63, grp = t >> 6;

    #pragma unroll
    for (int i = 0; i < 16; i++) {
        int id = t + i * 256;
        int p = id >> 6, q = id & 63;
        sGj[p * 64 + q] = g_G[(size_t)((0 * Bsz + b) * ND + d) * 4096 + id];
        sGi[p * 65 + q] = g_G[(size_t)((1 * Bsz + b) * ND + d) * 4096 + id];
    }
    __syncthreads();

    for (int side = 0; side < 2; side++) {
        const float* prel = (side == 0 ? p_rel_xj : p_rel_xi) + d * 4096;
        #pragma unroll
        for (int i = 0; i < 16; i++) sWR[t + i * 256] = prel[t + i * 256];
        if (t < 64) sOCS[t] = g_cs[((side * Bsz + b) * ND + d) * 64 + t];
        __syncthreads();

        const float* G = side ? sGi : sGj;
        int gs = side ? 65 : 64;
        float acc[4][4];
        #pragma unroll
        for (int i = 0; i < 4; i++)
            #pragma unroll
            for (int j = 0; j < 4; j++) acc[i][j] = 0.f;
        #pragma unroll 8
        for (int kk = 0; kk < 64; kk++) {
            float a0 = G[(prw + 0) * gs + kk];
            float a1 = G[(prw + 1) * gs + kk];
            float a2 = G[(prw + 2) * gs + kk];
            float a3 = G[(prw + 3) * gs + kk];
            float4 w4 = *(const float4*)&sWR[kk * 64 + qcw];
            acc[0][0] = fmaf(a0, w4.x, acc[0][0]); acc[0][1] = fmaf(a0, w4.y, acc[0][1]);
            acc[0][2] = fmaf(a0, w4.z, acc[0][2]); acc[0][3] = fmaf(a0, w4.w, acc[0][3]);
            acc[1][0] = fmaf(a1, w4.x, acc[1][0]); acc[1][1] = fmaf(a1, w4.y, acc[1][1]);
            acc[1][2] = fmaf(a1, w4.z, acc[1][2]); acc[1][3] = fmaf(a1, w4.w, acc[1][3]);
            acc[2][0] = fmaf(a2, w4.x, acc[2][0]); acc[2][1] = fmaf(a2, w4.y, acc[2][1]);
            acc[2][2] = fmaf(a2, w4.z, acc[2][2]); acc[2][3] = fmaf(a2, w4.w, acc[2][3]);
            acc[3][0] = fmaf(a3, w4.x, acc[3][0]); acc[3][1] = fmaf(a3, w4.y, acc[3][1]);
            acc[3][2] = fmaf(a3, w4.z, acc[3][2]); acc[3][3] = fmaf(a3, w4.w, acc[3][3]);
        }
        __syncthreads();
        #pragma unroll
        for (int i = 0; i < 4; i++)
            #pragma unroll
            for (int j = 0; j < 4; j++)
                sWR[(prw + i) * 64 + qcw + j] = expf(acc[i][j]);
        __syncthreads();

        float s = 0.f;
        #pragma unroll
        for (int r = 0; r < 16; r++) s += sWR[(grp * 16 + r) * 64 + col];
        red[t] = s; __syncthreads();
        if (t < 64) sCS[t] = red[t] + red[t + 64] + red[t + 128] + red[t + 192];
        __syncthreads();
        if (t == 0) {
            float tp = 0.f, to = 0.f;
            for (int i = 0; i < 64; i++) { tp += sCS[i]; to += sOCS[i]; }
            sTOT[0] = tp; sTOT[1] = to;
        }
        __syncthreads();
        if (t < 64) {
            float f = sqrtf((sOCS[t] * sTOT[0]) / (sTOT[1] * sCS[t]));
            (side ? sfi : sfj)[t] = f;
        }
        __syncthreads();
    }

    float xb[16]; float s = 0.f, ss = 0.f;
    #pragma unroll
    for (int i = 0; i < 16; i++) {
        int id = t + i * 256;
        int p = id >> 6, q = id & 63;
        float v = sGj[p * 64 + q] * sfj[p] + sGi[q * 65 + p] * sfi[q];
        xb[i] = v; s += v; ss += v * v;
    }
    red[t] = s; red2[t] = ss; __syncthreads();
    for (int off = 128; off > 0; off >>= 1) {
        if (t < off) { red[t] += red[t + off]; red2[t] += red2[t + off]; }
        __syncthreads();
    }
    float n = 4096.f;
    float mean = red[0] / n;
    float var  = (red2[0] - red[0] * red[0] / n) / (n - 1.f);
    float istd = 1.f / (sqrtf(var) + 1e-5f);
    float* ob = g_xbd + (size_t)(d * Bsz + b) * 4096;
    #pragma unroll
    for (int i = 0; i < 16; i++)
        ob[t + i * 256] = (xb[i] - mean) * istd * xstd + xmean;
}

// ---------------- accumulate per-depth contributions (fixed d order) ---------
__global__ void __launch_bounds__(256) accum_kernel(float* __restrict__ out) {
    int i = blockIdx.x * 256 + threadIdx.x;      // 0 .. Bsz*4096-1
    int b = i >> 12, idx = i & 4095;
    float s = 0.f;
    #pragma unroll
    for (int d = 0; d < ND; d++)
        s += g_xbd[(size_t)(d * Bsz + b) * 4096 + idx];
    out[i] = s;
}

// ---------------- launcher ---------------------------------------------------
extern "C" void kernel_launch(void* const* d_in, const int* in_sizes, int n_in,
                              void* d_out, int out_size) {
    const float* x        = (const float*)d_in[0];
    const float* o_xj     = (const float*)d_in[1];
    const float* o_xi     = (const float*)d_in[2];
    const float* p_xj     = (const float*)d_in[3];
    const float* p_xi     = (const float*)d_in[4];
    const float* o_rel_xj = (const float*)d_in[5];
    const float* o_rel_xi = (const float*)d_in[6];
    const float* p_rel_xj = (const float*)d_in[7];
    const float* p_rel_xi = (const float*)d_in[8];
    float* out = (float*)d_out;

    cudaFuncSetAttribute(final_depth, cudaFuncAttributeMaxDynamicSharedMemorySize,
                         FINAL_SMEM_FLOATS * sizeof(float));
    cudaFuncSetAttribute(gemm_mma<0>, cudaFuncAttributeMaxDynamicSharedMemorySize,
                         GEMM_DYNSM);
    cudaFuncSetAttribute(gemm_mma<1>, cudaFuncAttributeMaxDynamicSharedMemorySize,
                         GEMM_DYNSM);
    cudaFuncSetAttribute(stage2_mma, cudaFuncAttributeMaxDynamicSharedMemorySize,
                         S2_DYNSM);

    // gemm_mma<0> is launch #4 so ncu (-s 5 -c 1) profiles it
    convw_kernel<<<dim3(512, 2), 256>>>(o_xj, o_rel_xj, o_xi, o_rel_xi);
    convp_kernel<<<dim3(512, 2), 256>>>(p_xj, p_xi);
    convx_kernel<<<dim3(16, Bsz), 256>>>(x);
    gemm_mma<0><<<dim3(16, Bsz), 128, GEMM_DYNSM>>>();
    gemm_mma<1><<<dim3(16, Bsz), 128, GEMM_DYNSM>>>();
    csred_kernel<<<256, 256>>>();
    stage2_mma<<<dim3(ND, 2, Bsz), 128, S2_DYNSM>>>();
    final_depth<<<dim3(ND, Bsz), 256, FINAL_SMEM_FLOATS * sizeof(float)>>>(p_rel_xj, p_rel_xi);
    accum_kernel<<<Bsz * 4096 / 256, 256>>>(out);
}